// round 2
// baseline (speedup 1.0000x reference)
#include <cuda_runtime.h>
#include <math.h>

#define BB 256     // batch
#define HH 512     // hidden
#define VV 100     // vocab
#define TT 200     // steps

// Scratch: full hidden-state history h_1..h_200 (200*256*512 fp32 = 104.9 MB)
__device__ float g_hist[(size_t)TT * BB * HH];

__device__ __forceinline__ float sigmoidf_(float x) {
    return 1.0f / (1.0f + expf(-x));
}

// ---------------------------------------------------------------------------
// Fused GRU step: computes h_new[b,j] for a 32(b) x 32(j) tile.
// Six K=512 dot products per output (gi: r,z,n from x; gh: r,z,n from h),
// then the GRU gate combine. Grid: (H/32=16, B/32=8) = 128 blocks, 256 thr.
// ---------------------------------------------------------------------------
__global__ __launch_bounds__(256) void gru_step_kernel(
    const float* __restrict__ x, int xs,          // x row stride (0 = broadcast row)
    const float* __restrict__ h,
    const float* __restrict__ w_ih,               // [3H, H]
    const float* __restrict__ w_hh,               // [3H, H]
    const float* __restrict__ b_ih,               // [3H]
    const float* __restrict__ b_hh,               // [3H]
    float* __restrict__ h_out)
{
    __shared__ float sX[32][32];          // [b][k]
    __shared__ float sH[32][32];          // [b][k]
    __shared__ float sWih[3][32][32];     // [gate][k][j]  (k-major: conflict-free reads)
    __shared__ float sWhh[3][32][32];

    const int tid = threadIdx.x;
    const int tj  = tid & 31;             // j within tile
    const int tb  = tid >> 5;             // 0..7 -> 4 b-rows each
    const int j0  = blockIdx.x * 32;
    const int b0  = blockIdx.y * 32;

    float acc[4][6];
    #pragma unroll
    for (int i = 0; i < 4; i++)
        #pragma unroll
        for (int g = 0; g < 6; g++) acc[i][g] = 0.0f;

    const int lb  = tid >> 3;             // 0..31 tile row for loads
    const int lk4 = (tid & 7) * 4;        // float4 k-offset

    for (int k0 = 0; k0 < HH; k0 += 32) {
        // --- load input tiles (coalesced float4) ---
        float4 xv4 = *(const float4*)(x + (size_t)(b0 + lb) * (size_t)xs + k0 + lk4);
        *(float4*)&sX[lb][lk4] = xv4;
        float4 hv4 = *(const float4*)(h + (size_t)(b0 + lb) * HH + k0 + lk4);
        *(float4*)&sH[lb][lk4] = hv4;
        // --- load weight tiles, transposed to [k][j] in smem ---
        #pragma unroll
        for (int g = 0; g < 3; g++) {
            float4 wi = *(const float4*)(w_ih + (size_t)(g * HH + j0 + lb) * HH + k0 + lk4);
            sWih[g][lk4 + 0][lb] = wi.x;
            sWih[g][lk4 + 1][lb] = wi.y;
            sWih[g][lk4 + 2][lb] = wi.z;
            sWih[g][lk4 + 3][lb] = wi.w;
            float4 wh = *(const float4*)(w_hh + (size_t)(g * HH + j0 + lb) * HH + k0 + lk4);
            sWhh[g][lk4 + 0][lb] = wh.x;
            sWhh[g][lk4 + 1][lb] = wh.y;
            sWhh[g][lk4 + 2][lb] = wh.z;
            sWhh[g][lk4 + 3][lb] = wh.w;
        }
        __syncthreads();

        #pragma unroll
        for (int kk = 0; kk < 32; kk++) {
            const float wi0 = sWih[0][kk][tj];
            const float wi1 = sWih[1][kk][tj];
            const float wi2 = sWih[2][kk][tj];
            const float wh0 = sWhh[0][kk][tj];
            const float wh1 = sWhh[1][kk][tj];
            const float wh2 = sWhh[2][kk][tj];
            #pragma unroll
            for (int i = 0; i < 4; i++) {
                const float xv = sX[tb * 4 + i][kk];   // broadcast within warp
                const float hv = sH[tb * 4 + i][kk];
                acc[i][0] += xv * wi0;
                acc[i][1] += xv * wi1;
                acc[i][2] += xv * wi2;
                acc[i][3] += hv * wh0;
                acc[i][4] += hv * wh1;
                acc[i][5] += hv * wh2;
            }
        }
        __syncthreads();
    }

    // --- gate combine (torch GRU order: r, z, n) ---
    const int j = j0 + tj;
    const float bir  = b_ih[j],          bhr = b_hh[j];
    const float biz  = b_ih[HH + j],     bhz = b_hh[HH + j];
    const float bin_ = b_ih[2 * HH + j], bhn = b_hh[2 * HH + j];
    #pragma unroll
    for (int i = 0; i < 4; i++) {
        const int b = b0 + tb * 4 + i;
        const float r = sigmoidf_(acc[i][0] + bir + acc[i][3] + bhr);
        const float z = sigmoidf_(acc[i][1] + biz + acc[i][4] + bhz);
        const float n = tanhf(acc[i][2] + bin_ + r * (acc[i][5] + bhn));
        const float hp = h[(size_t)b * HH + j];
        h_out[(size_t)b * HH + j] = (1.0f - z) * n + z * hp;
    }
}

// ---------------------------------------------------------------------------
// Projection: out[b][v][t] = hist[t][b][:] . proj_w[v][:] + proj_b[v]
// One block per b (256 blocks). Block tile = 200 t x 100 v, K chunked by 32.
// 512 threads; 500 active compute threads: 25 t-groups x 20 v-groups,
// each thread: 8 t (stride 25) x 5 v.
// ---------------------------------------------------------------------------
__global__ __launch_bounds__(512) void proj_kernel(
    const float* __restrict__ proj_w,   // [V, H]
    const float* __restrict__ proj_b,   // [V]
    float* __restrict__ out)            // [B, V, T]
{
    __shared__ float sH[TT][33];        // padded: conflict-free strided reads
    __shared__ float sW[VV][33];

    const int b   = blockIdx.x;
    const int tid = threadIdx.x;
    const int tg  = tid % 25;           // t-group
    const int vg  = tid / 25;           // 0..20 (20 active)
    const bool active = (tid < 500);

    float acc[8][5];
    #pragma unroll
    for (int i = 0; i < 8; i++)
        #pragma unroll
        for (int jv = 0; jv < 5; jv++) acc[i][jv] = 0.0f;

    for (int k0 = 0; k0 < HH; k0 += 32) {
        for (int idx = tid; idx < TT * 32; idx += 512) {
            const int t = idx >> 5, k = idx & 31;
            sH[t][k] = g_hist[((size_t)t * BB + b) * HH + k0 + k];
        }
        for (int idx = tid; idx < VV * 32; idx += 512) {
            const int v = idx >> 5, k = idx & 31;
            sW[v][k] = proj_w[(size_t)v * HH + k0 + k];
        }
        __syncthreads();

        if (active) {
            #pragma unroll
            for (int kk = 0; kk < 32; kk++) {
                float wv[5];
                #pragma unroll
                for (int jv = 0; jv < 5; jv++) wv[jv] = sW[vg * 5 + jv][kk];
                #pragma unroll
                for (int i = 0; i < 8; i++) {
                    const float hv = sH[tg + 25 * i][kk];
                    #pragma unroll
                    for (int jv = 0; jv < 5; jv++) acc[i][jv] += hv * wv[jv];
                }
            }
        }
        __syncthreads();
    }

    if (active) {
        float pb[5];
        #pragma unroll
        for (int jv = 0; jv < 5; jv++) pb[jv] = proj_b[vg * 5 + jv];
        #pragma unroll
        for (int i = 0; i < 8; i++) {
            const int t = tg + 25 * i;
            #pragma unroll
            for (int jv = 0; jv < 5; jv++) {
                const int v = vg * 5 + jv;
                out[((size_t)b * VV + v) * TT + t] = acc[i][jv] + pb[jv];
            }
        }
    }
}

// ---------------------------------------------------------------------------
extern "C" void kernel_launch(void* const* d_in, const int* in_sizes, int n_in,
                              void* d_out, int out_size)
{
    (void)in_sizes; (void)n_in; (void)out_size;
    const float* feat   = (const float*)d_in[0];   // [B, H]
    const float* embed  = (const float*)d_in[1];   // [V, H]
    const float* w_ih   = (const float*)d_in[2];   // [3H, H]
    const float* w_hh   = (const float*)d_in[3];   // [3H, H]
    const float* b_ih   = (const float*)d_in[4];   // [3H]
    const float* b_hh   = (const float*)d_in[5];   // [3H]
    const float* proj_w = (const float*)d_in[6];   // [V, H]
    const float* proj_b = (const float*)d_in[7];   // [V]
    float* out = (float*)d_out;

    float* hist = nullptr;
    cudaGetSymbolAddress((void**)&hist, g_hist);

    const dim3 grid_step(HH / 32, BB / 32);  // (16, 8)

    // step 0: x = embed_table[SOS=0] broadcast (row stride 0), h = feat
    gru_step_kernel<<<grid_step, 256>>>(embed, 0, feat,
                                        w_ih, w_hh, b_ih, b_hh, hist);
    // steps 1..199: x == h == hist[t-1]
    for (int t = 1; t < TT; t++) {
        const float* hprev = hist + (size_t)(t - 1) * BB * HH;
        gru_step_kernel<<<grid_step, 256>>>(hprev, HH, hprev,
                                            w_ih, w_hh, b_ih, b_hh,
                                            hist + (size_t)t * BB * HH);
    }
    // final projection
    proj_kernel<<<BB, 512>>>(proj_w, proj_b, out);
}

// round 4
// speedup vs baseline: 1.6003x; 1.6003x over previous
#include <cuda_runtime.h>
#include <stdint.h>
#include <math.h>

#define BB 256     // batch
#define HH 512     // hidden
#define VV 100     // vocab
#define TT 200     // steps

// Scratch: full hidden-state history h_1..h_200 (200*256*512 fp32 = 104.9 MB)
__device__ float g_hist[(size_t)TT * BB * HH];

__device__ __forceinline__ float sigmoidf_(float x) {
    return 1.0f / (1.0f + expf(-x));
}

// ---------------------------------------------------------------------------
// cp.async helpers
// ---------------------------------------------------------------------------
__device__ __forceinline__ void cp_async16(float* smem_dst, const float* gmem_src) {
    unsigned int s = (unsigned int)__cvta_generic_to_shared(smem_dst);
    asm volatile("cp.async.cg.shared.global [%0], [%1], 16;\n" :: "r"(s), "l"(gmem_src));
}
#define CP_COMMIT() asm volatile("cp.async.commit_group;\n" ::: "memory")
#define CP_WAIT(n)  asm volatile("cp.async.wait_group %0;\n" :: "n"(n) : "memory")

// ---------------------------------------------------------------------------
// Fast GRU step for t>=1 (input x == h_prev).
// Grid: (512/16 j-tiles = 32, 256/32 b-tiles = 8) = 256 blocks, 128 threads.
// Block computes h_new for 32 batch rows x 16 hidden cols (6 gate dots each).
// Per-thread micro-tile: 4 batch x 6 gates (24 fp32 accumulators), float4
// vectorized smem reads, cp.async double-buffered K-chunks of 32.
// ---------------------------------------------------------------------------
__global__ __launch_bounds__(128) void gru_step_fast(
    const float* __restrict__ h_prev,             // [B, H]
    const float* __restrict__ w_ih,               // [3H, H]
    const float* __restrict__ w_hh,               // [3H, H]
    const float* __restrict__ b_ih,               // [3H]
    const float* __restrict__ b_hh,               // [3H]
    float* __restrict__ h_out)                    // [B, H]
{
    // padded rows (36 floats = 144B, multiple of 16B, bank-offset 4/row)
    __shared__ __align__(16) float sW[2][6][16][36];   // [buf][gate][j][k]
    __shared__ __align__(16) float sH[2][32][36];      // [buf][b][k]

    const int tid  = threadIdx.x;
    const int lane = tid & 31;
    const int warp = tid >> 5;          // 0..3
    const int jj   = lane & 15;         // j within tile
    const int half = lane >> 4;         // 0/1
    const int j0   = blockIdx.x * 16;
    const int b0   = blockIdx.y * 32;
    const int bl   = warp * 8 + half * 4;   // local batch base (4 rows)

    // --- per-thread cp.async descriptors (chunk-invariant parts) ---
    // W: 96 rows (6 gate-mats x 16 j) x 8 float4 per 32-k chunk = 768 f4; 6/thread
    const float* wg[6];
    int          wso[6];
    #pragma unroll
    for (int n = 0; n < 6; n++) {
        const int f   = tid + 128 * n;
        const int row = f >> 3;          // 0..95
        const int c4  = f & 7;
        const int g   = row >> 4;        // 0..5
        const int j   = row & 15;
        const float* mat = (g < 3) ? w_ih : w_hh;
        const int    gr  = ((g < 3) ? g : g - 3) * HH + j0 + j;
        wg[n]  = mat + (size_t)gr * HH + c4 * 4;
        wso[n] = (g * 16 + j) * 36 + c4 * 4;
    }
    // H: 32 rows x 8 f4 = 256 f4; 2/thread
    const float* hg[2];
    int          hso[2];
    #pragma unroll
    for (int n = 0; n < 2; n++) {
        const int f  = tid + 128 * n;
        const int b  = f >> 3;
        const int c4 = f & 7;
        hg[n]  = h_prev + (size_t)(b0 + b) * HH + c4 * 4;
        hso[n] = b * 36 + c4 * 4;
    }

    float acc[4][6];
    #pragma unroll
    for (int i = 0; i < 4; i++)
        #pragma unroll
        for (int g = 0; g < 6; g++) acc[i][g] = 0.0f;

    // --- prologue: issue chunk 0 ---
    {
        float* swb = &sW[0][0][0][0];
        float* shb = &sH[0][0][0];
        #pragma unroll
        for (int n = 0; n < 6; n++) cp_async16(swb + wso[n], wg[n]);
        #pragma unroll
        for (int n = 0; n < 2; n++) cp_async16(shb + hso[n], hg[n]);
        CP_COMMIT();
    }

    const int NCH = HH / 32;   // 16 chunks
    for (int c = 0; c < NCH; c++) {
        const int buf = c & 1;
        if (c + 1 < NCH) {
            const int nb = (c + 1) & 1;
            const int k0 = (c + 1) * 32;
            float* swb = &sW[nb][0][0][0];
            float* shb = &sH[nb][0][0];
            #pragma unroll
            for (int n = 0; n < 6; n++) cp_async16(swb + wso[n], wg[n] + k0);
            #pragma unroll
            for (int n = 0; n < 2; n++) cp_async16(shb + hso[n], hg[n] + k0);
            CP_COMMIT();
            CP_WAIT(1);
        } else {
            CP_WAIT(0);
        }
        __syncthreads();

        const float* swb = &sW[buf][0][0][0];
        #pragma unroll
        for (int kq = 0; kq < 8; kq++) {
            float4 w4[6];
            #pragma unroll
            for (int g = 0; g < 6; g++)
                w4[g] = *(const float4*)(swb + (g * 16 + jj) * 36 + kq * 4);
            #pragma unroll
            for (int i = 0; i < 4; i++) {
                const float4 a = *(const float4*)(&sH[buf][bl + i][kq * 4]);
                #pragma unroll
                for (int g = 0; g < 6; g++) {
                    acc[i][g] += a.x * w4[g].x;
                    acc[i][g] += a.y * w4[g].y;
                    acc[i][g] += a.z * w4[g].z;
                    acc[i][g] += a.w * w4[g].w;
                }
            }
        }
        __syncthreads();
    }

    // --- fused gate epilogue (torch GRU order r, z, n) ---
    const int j = j0 + jj;
    const float bir  = b_ih[j],          bhr = b_hh[j];
    const float biz  = b_ih[HH + j],     bhz = b_hh[HH + j];
    const float bin_ = b_ih[2 * HH + j], bhn = b_hh[2 * HH + j];
    #pragma unroll
    for (int i = 0; i < 4; i++) {
        const int b = b0 + bl + i;
        const float r = sigmoidf_(acc[i][0] + bir + acc[i][3] + bhr);
        const float z = sigmoidf_(acc[i][1] + biz + acc[i][4] + bhz);
        const float n = tanhf(acc[i][2] + bin_ + r * (acc[i][5] + bhn));
        const float hp = h_prev[(size_t)b * HH + j];
        h_out[(size_t)b * HH + j] = (1.0f - z) * n + z * hp;
    }
}

// ---------------------------------------------------------------------------
// Generic GRU step (x may differ from h) — used only for t = 0.
// ---------------------------------------------------------------------------
__global__ __launch_bounds__(256) void gru_step_kernel(
    const float* __restrict__ x, int xs,          // x row stride (0 = broadcast row)
    const float* __restrict__ h,
    const float* __restrict__ w_ih,
    const float* __restrict__ w_hh,
    const float* __restrict__ b_ih,
    const float* __restrict__ b_hh,
    float* __restrict__ h_out)
{
    __shared__ float sX[32][32];
    __shared__ float sH[32][32];
    __shared__ float sWih[3][32][32];
    __shared__ float sWhh[3][32][32];

    const int tid = threadIdx.x;
    const int tj  = tid & 31;
    const int tb  = tid >> 5;
    const int j0  = blockIdx.x * 32;
    const int b0  = blockIdx.y * 32;

    float acc[4][6];
    #pragma unroll
    for (int i = 0; i < 4; i++)
        #pragma unroll
        for (int g = 0; g < 6; g++) acc[i][g] = 0.0f;

    const int lb  = tid >> 3;
    const int lk4 = (tid & 7) * 4;

    for (int k0 = 0; k0 < HH; k0 += 32) {
        float4 xv4 = *(const float4*)(x + (size_t)(b0 + lb) * (size_t)xs + k0 + lk4);
        *(float4*)&sX[lb][lk4] = xv4;
        float4 hv4 = *(const float4*)(h + (size_t)(b0 + lb) * HH + k0 + lk4);
        *(float4*)&sH[lb][lk4] = hv4;
        #pragma unroll
        for (int g = 0; g < 3; g++) {
            float4 wi = *(const float4*)(w_ih + (size_t)(g * HH + j0 + lb) * HH + k0 + lk4);
            sWih[g][lk4 + 0][lb] = wi.x;
            sWih[g][lk4 + 1][lb] = wi.y;
            sWih[g][lk4 + 2][lb] = wi.z;
            sWih[g][lk4 + 3][lb] = wi.w;
            float4 wh = *(const float4*)(w_hh + (size_t)(g * HH + j0 + lb) * HH + k0 + lk4);
            sWhh[g][lk4 + 0][lb] = wh.x;
            sWhh[g][lk4 + 1][lb] = wh.y;
            sWhh[g][lk4 + 2][lb] = wh.z;
            sWhh[g][lk4 + 3][lb] = wh.w;
        }
        __syncthreads();

        #pragma unroll
        for (int kk = 0; kk < 32; kk++) {
            const float wi0 = sWih[0][kk][tj];
            const float wi1 = sWih[1][kk][tj];
            const float wi2 = sWih[2][kk][tj];
            const float wh0 = sWhh[0][kk][tj];
            const float wh1 = sWhh[1][kk][tj];
            const float wh2 = sWhh[2][kk][tj];
            #pragma unroll
            for (int i = 0; i < 4; i++) {
                const float xv = sX[tb * 4 + i][kk];
                const float hv = sH[tb * 4 + i][kk];
                acc[i][0] += xv * wi0;
                acc[i][1] += xv * wi1;
                acc[i][2] += xv * wi2;
                acc[i][3] += hv * wh0;
                acc[i][4] += hv * wh1;
                acc[i][5] += hv * wh2;
            }
        }
        __syncthreads();
    }

    const int j = j0 + tj;
    const float bir  = b_ih[j],          bhr = b_hh[j];
    const float biz  = b_ih[HH + j],     bhz = b_hh[HH + j];
    const float bin_ = b_ih[2 * HH + j], bhn = b_hh[2 * HH + j];
    #pragma unroll
    for (int i = 0; i < 4; i++) {
        const int b = b0 + tb * 4 + i;
        const float r = sigmoidf_(acc[i][0] + bir + acc[i][3] + bhr);
        const float z = sigmoidf_(acc[i][1] + biz + acc[i][4] + bhz);
        const float n = tanhf(acc[i][2] + bin_ + r * (acc[i][5] + bhn));
        const float hp = h[(size_t)b * HH + j];
        h_out[(size_t)b * HH + j] = (1.0f - z) * n + z * hp;
    }
}

// ---------------------------------------------------------------------------
// Projection: out[b][v][t] = hist[t][b][:] . proj_w[v][:] + proj_b[v]
// ---------------------------------------------------------------------------
__global__ __launch_bounds__(512) void proj_kernel(
    const float* __restrict__ proj_w,   // [V, H]
    const float* __restrict__ proj_b,   // [V]
    float* __restrict__ out)            // [B, V, T]
{
    __shared__ float sH[TT][33];
    __shared__ float sW[VV][33];

    const int b   = blockIdx.x;
    const int tid = threadIdx.x;
    const int tg  = tid % 25;
    const int vg  = tid / 25;
    const bool active = (tid < 500);

    float acc[8][5];
    #pragma unroll
    for (int i = 0; i < 8; i++)
        #pragma unroll
        for (int jv = 0; jv < 5; jv++) acc[i][jv] = 0.0f;

    for (int k0 = 0; k0 < HH; k0 += 32) {
        for (int idx = tid; idx < TT * 32; idx += 512) {
            const int t = idx >> 5, k = idx & 31;
            sH[t][k] = g_hist[((size_t)t * BB + b) * HH + k0 + k];
        }
        for (int idx = tid; idx < VV * 32; idx += 512) {
            const int v = idx >> 5, k = idx & 31;
            sW[v][k] = proj_w[(size_t)v * HH + k0 + k];
        }
        __syncthreads();

        if (active) {
            #pragma unroll
            for (int kk = 0; kk < 32; kk++) {
                float wv[5];
                #pragma unroll
                for (int jv = 0; jv < 5; jv++) wv[jv] = sW[vg * 5 + jv][kk];
                #pragma unroll
                for (int i = 0; i < 8; i++) {
                    const float hv = sH[tg + 25 * i][kk];
                    #pragma unroll
                    for (int jv = 0; jv < 5; jv++) acc[i][jv] += hv * wv[jv];
                }
            }
        }
        __syncthreads();
    }

    if (active) {
        float pb[5];
        #pragma unroll
        for (int jv = 0; jv < 5; jv++) pb[jv] = proj_b[vg * 5 + jv];
        #pragma unroll
        for (int i = 0; i < 8; i++) {
            const int t = tg + 25 * i;
            #pragma unroll
            for (int jv = 0; jv < 5; jv++) {
                const int v = vg * 5 + jv;
                out[((size_t)b * VV + v) * TT + t] = acc[i][jv] + pb[jv];
            }
        }
    }
}

// ---------------------------------------------------------------------------
extern "C" void kernel_launch(void* const* d_in, const int* in_sizes, int n_in,
                              void* d_out, int out_size)
{
    (void)in_sizes; (void)n_in; (void)out_size;
    const float* feat   = (const float*)d_in[0];   // [B, H]
    const float* embed  = (const float*)d_in[1];   // [V, H]
    const float* w_ih   = (const float*)d_in[2];   // [3H, H]
    const float* w_hh   = (const float*)d_in[3];   // [3H, H]
    const float* b_ih   = (const float*)d_in[4];   // [3H]
    const float* b_hh   = (const float*)d_in[5];   // [3H]
    const float* proj_w = (const float*)d_in[6];   // [V, H]
    const float* proj_b = (const float*)d_in[7];   // [V]
    float* out = (float*)d_out;

    float* hist = nullptr;
    cudaGetSymbolAddress((void**)&hist, g_hist);

    // step 0: x = embed_table[SOS=0] broadcast (row stride 0), h = feat
    gru_step_kernel<<<dim3(HH / 32, BB / 32), 256>>>(embed, 0, feat,
                                                     w_ih, w_hh, b_ih, b_hh, hist);
    // steps 1..199: x == h == hist[t-1]  (fast fused kernel)
    const dim3 grid_fast(HH / 16, BB / 32);  // (32, 8) = 256 blocks
    for (int t = 1; t < TT; t++) {
        const float* hprev = hist + (size_t)(t - 1) * BB * HH;
        gru_step_fast<<<grid_fast, 128>>>(hprev, w_ih, w_hh, b_ih, b_hh,
                                          hist + (size_t)t * BB * HH);
    }
    // final projection
    proj_kernel<<<BB, 512>>>(proj_w, proj_b, out);
}

// round 5
// speedup vs baseline: 3.3756x; 2.1094x over previous
#include <cuda_runtime.h>
#include <cuda_bf16.h>
#include <stdint.h>
#include <math.h>

#define BB 256     // batch
#define HH 512     // hidden
#define VV 100     // vocab
#define TT 200     // steps

// fp32 hidden-state history (proj + epilogue need fp32 h)
__device__ float g_hist[(size_t)TT * BB * HH];
// bf16 hi/lo ping-pong of previous hidden state
__device__ __nv_bfloat16 g_hh[2][BB * HH];
__device__ __nv_bfloat16 g_hl[2][BB * HH];
// packed weights: row n = jb*96 + g*16 + j  (jb=0..31, g=0..5, j=0..15), k=0..511
__device__ __nv_bfloat16 g_wh[6 * HH * HH];
__device__ __nv_bfloat16 g_wl[6 * HH * HH];

__device__ __forceinline__ float sigmoidf_(float x) {
    return 1.0f / (1.0f + expf(-x));
}

// ---------------------------------------------------------------------------
// async / mma helpers
// ---------------------------------------------------------------------------
__device__ __forceinline__ void cp_async16(void* smem_dst, const void* gmem_src) {
    unsigned int s = (unsigned int)__cvta_generic_to_shared(smem_dst);
    asm volatile("cp.async.cg.shared.global [%0], [%1], 16;\n" :: "r"(s), "l"(gmem_src));
}
#define CP_COMMIT() asm volatile("cp.async.commit_group;\n" ::: "memory")
#define CP_WAIT(n)  asm volatile("cp.async.wait_group %0;\n" :: "n"(n) : "memory")

__device__ __forceinline__ void ldsm4(uint32_t r[4], const void* p) {
    unsigned int s = (unsigned int)__cvta_generic_to_shared(p);
    asm volatile("ldmatrix.sync.aligned.m8n8.x4.shared.b16 {%0,%1,%2,%3}, [%4];"
                 : "=r"(r[0]), "=r"(r[1]), "=r"(r[2]), "=r"(r[3]) : "r"(s));
}

__device__ __forceinline__ void mma_bf16(float d[4], const uint32_t a[4],
                                         uint32_t b0, uint32_t b1) {
    asm volatile(
        "mma.sync.aligned.m16n8k16.row.col.f32.bf16.bf16.f32 "
        "{%0,%1,%2,%3}, {%4,%5,%6,%7}, {%8,%9}, {%0,%1,%2,%3};"
        : "+f"(d[0]), "+f"(d[1]), "+f"(d[2]), "+f"(d[3])
        : "r"(a[0]), "r"(a[1]), "r"(a[2]), "r"(a[3]), "r"(b0), "r"(b1));
}

// ---------------------------------------------------------------------------
// One-time weight prep: pack [w_ih; w_hh] into MMA-friendly row order and
// split each fp32 weight into bf16 hi + lo.
// packed row n = jb*96 + g*16 + j  ->  original row (g%3)*512 + jb*16 + j
// of (g<3 ? w_ih : w_hh)
// ---------------------------------------------------------------------------
__global__ __launch_bounds__(256) void prep_weights(
    const float* __restrict__ w_ih, const float* __restrict__ w_hh)
{
    int idx = blockIdx.x * 256 + threadIdx.x;
    if (idx >= 6 * HH * HH) return;
    int n = idx / HH, k = idx % HH;
    int jb = n / 96, rr = n % 96, g = rr / 16, j = rr % 16;
    const float* src = (g < 3) ? w_ih : w_hh;
    float v = src[(size_t)((g % 3) * HH + jb * 16 + j) * HH + k];
    __nv_bfloat16 hi = __float2bfloat16(v);
    g_wh[idx] = hi;
    g_wl[idx] = __float2bfloat16(v - __bfloat162float(hi));
}

// ---------------------------------------------------------------------------
// Convert fp32 h -> bf16 hi/lo (used once after step 0)
// ---------------------------------------------------------------------------
__global__ __launch_bounds__(256) void convert_h(
    const float* __restrict__ h, __nv_bfloat16* __restrict__ hh,
    __nv_bfloat16* __restrict__ hl)
{
    int idx = blockIdx.x * 256 + threadIdx.x;
    if (idx >= BB * HH) return;
    float v = h[idx];
    __nv_bfloat16 hi = __float2bfloat16(v);
    hh[idx] = hi;
    hl[idx] = __float2bfloat16(v - __bfloat162float(hi));
}

// ---------------------------------------------------------------------------
// Tensor-core GRU step (t >= 1): G = h_prev @ [Wih;Whh]^T via 3-term bf16
// split MMA, fused gate epilogue.
// Grid: (32 j-tiles, 4 b-tiles) = 128 blocks, 256 threads (8 warps, 4m x 2n).
// Block tile: 64 batch x 96 n (16 j x 6 gates). K chunked by 64, double buf.
// ---------------------------------------------------------------------------
#define KCH   64
#define RS    72                       // smem row stride (bf16): conflict-free
#define A_MAT (64 * RS)                // 4608 bf16 per A matrix
#define B_MAT (96 * RS)                // 6912 bf16 per B matrix
#define BUFSZ (2 * A_MAT + 2 * B_MAT)  // 23040 bf16 per buffer
#define SMEM_BYTES (2 * BUFSZ * 2)     // 92160 bytes

__global__ __launch_bounds__(256) void gru_step_mma(
    const float* __restrict__ h_prev,            // [B, H] fp32
    const __nv_bfloat16* __restrict__ hh_prev,   // [B, H]
    const __nv_bfloat16* __restrict__ hl_prev,   // [B, H]
    const float* __restrict__ b_ih,
    const float* __restrict__ b_hh,
    float* __restrict__ h_out,
    __nv_bfloat16* __restrict__ hh_out,
    __nv_bfloat16* __restrict__ hl_out)
{
    extern __shared__ __align__(16) __nv_bfloat16 dsm[];

    const int tid  = threadIdx.x;
    const int lane = tid & 31;
    const int w    = tid >> 5;          // 0..7
    const int mw   = w & 3;             // m-warp: rows 16*mw .. 16*mw+15
    const int nv   = w >> 2;            // n-warp: cols 48*nv .. 48*nv+47
    const int jb   = blockIdx.x;        // 0..31
    const int b0   = blockIdx.y * 64;   // batch base

    // --- cp.async source/dest descriptors (chunk-invariant) ---
    // A: 1024 float4 per chunk (2 mats x 64 rows x 8) -> 4 per thread
    const __nv_bfloat16* a_src[4];
    int a_dst[4];
    #pragma unroll
    for (int n = 0; n < 4; n++) {
        int f   = tid + 256 * n;
        int mat = f >> 9;
        int row = (f >> 3) & 63;
        int c4  = f & 7;
        a_src[n] = (mat ? hl_prev : hh_prev) + (size_t)(b0 + row) * HH + c4 * 8;
        a_dst[n] = mat * A_MAT + row * RS + c4 * 8;
    }
    // B: 1536 float4 per chunk (2 mats x 96 rows x 8) -> 6 per thread
    const __nv_bfloat16* b_src[6];
    int b_dst[6];
    #pragma unroll
    for (int n = 0; n < 6; n++) {
        int f   = tid + 256 * n;
        int mat = f / 768;
        int rr  = f % 768;
        int row = rr >> 3;
        int c4  = rr & 7;
        const __nv_bfloat16* wsrc = mat ? g_wl : g_wh;
        b_src[n] = wsrc + (size_t)(jb * 96 + row) * HH + c4 * 8;
        b_dst[n] = 2 * A_MAT + mat * B_MAT + row * RS + c4 * 8;
    }

    // --- ldmatrix per-lane offsets (within a buffer, bf16 units) ---
    // A: lanes 0-7 rows 0-7 klo | 8-15 rows 8-15 klo | 16-23 rows 0-7 khi | 24-31 rows 8-15 khi
    const int a_row  = mw * 16 + (lane & 15);
    const int a_koff = (lane >> 4) * 8;
    // B: lanes 0-7 rows 0-7 klo | 8-15 rows 0-7 khi | 16-23 rows 8-15 klo | 24-31 rows 8-15 khi
    const int b_rowL = (lane & 7) + ((lane & 16) ? 8 : 0);
    const int b_koff = (lane & 8) ? 8 : 0;

    float acc[6][4];
    #pragma unroll
    for (int f = 0; f < 6; f++)
        #pragma unroll
        for (int i = 0; i < 4; i++) acc[f][i] = 0.0f;

    // --- prologue: chunk 0 ---
    {
        __nv_bfloat16* buf = dsm;
        #pragma unroll
        for (int n = 0; n < 4; n++) cp_async16(buf + a_dst[n], a_src[n]);
        #pragma unroll
        for (int n = 0; n < 6; n++) cp_async16(buf + b_dst[n], b_src[n]);
        CP_COMMIT();
    }

    const int NCH = HH / KCH;   // 8
    for (int c = 0; c < NCH; c++) {
        if (c + 1 < NCH) {
            __nv_bfloat16* buf = dsm + ((c + 1) & 1) * BUFSZ;
            const int k0 = (c + 1) * KCH;
            #pragma unroll
            for (int n = 0; n < 4; n++) cp_async16(buf + a_dst[n], a_src[n] + k0);
            #pragma unroll
            for (int n = 0; n < 6; n++) cp_async16(buf + b_dst[n], b_src[n] + k0);
            CP_COMMIT();
            CP_WAIT(1);
        } else {
            CP_WAIT(0);
        }
        __syncthreads();

        __nv_bfloat16* buf = dsm + (c & 1) * BUFSZ;
        __nv_bfloat16* sAh = buf;
        __nv_bfloat16* sAl = buf + A_MAT;
        __nv_bfloat16* sBh = buf + 2 * A_MAT;
        __nv_bfloat16* sBl = buf + 2 * A_MAT + B_MAT;

        #pragma unroll
        for (int q = 0; q < KCH / 16; q++) {        // 4 k16 steps
            uint32_t aH[4], aL[4];
            const int ak = q * 16 + a_koff;
            ldsm4(aH, sAh + a_row * RS + ak);
            ldsm4(aL, sAl + a_row * RS + ak);
            #pragma unroll
            for (int p = 0; p < 3; p++) {           // pairs of n8 tiles
                const int brow = nv * 48 + p * 16 + b_rowL;
                const int bk   = q * 16 + b_koff;
                uint32_t bh[4], bl[4];
                ldsm4(bh, sBh + brow * RS + bk);
                ldsm4(bl, sBl + brow * RS + bk);
                mma_bf16(acc[2 * p],     aH, bh[0], bh[1]);
                mma_bf16(acc[2 * p],     aH, bl[0], bl[1]);
                mma_bf16(acc[2 * p],     aL, bh[0], bh[1]);
                mma_bf16(acc[2 * p + 1], aH, bh[2], bh[3]);
                mma_bf16(acc[2 * p + 1], aH, bl[2], bl[3]);
                mma_bf16(acc[2 * p + 1], aL, bh[2], bh[3]);
            }
        }
        __syncthreads();
    }

    // --- write frags to smem G[64][96] (aliases buffers; all waits done) ---
    float* sG = (float*)dsm;
    {
        const int r  = mw * 16 + (lane >> 2);
        #pragma unroll
        for (int f = 0; f < 6; f++) {
            const int cb = nv * 48 + f * 8 + (lane & 3) * 2;
            sG[r * 96 + cb]           = acc[f][0];
            sG[r * 96 + cb + 1]       = acc[f][1];
            sG[(r + 8) * 96 + cb]     = acc[f][2];
            sG[(r + 8) * 96 + cb + 1] = acc[f][3];
        }
    }
    __syncthreads();

    // --- gate epilogue: 64 b x 16 j outputs ---
    for (int e = tid; e < 64 * 16; e += 256) {
        const int b = e >> 4, j = e & 15;
        const float g0 = sG[b * 96 + j];
        const float g1 = sG[b * 96 + 16 + j];
        const float g2 = sG[b * 96 + 32 + j];
        const float g3 = sG[b * 96 + 48 + j];
        const float g4 = sG[b * 96 + 64 + j];
        const float g5 = sG[b * 96 + 80 + j];
        const int jg = jb * 16 + j;
        const int bg = b0 + b;
        const float r = sigmoidf_(g0 + b_ih[jg] + g3 + b_hh[jg]);
        const float z = sigmoidf_(g1 + b_ih[HH + jg] + g4 + b_hh[HH + jg]);
        const float n = tanhf(g2 + b_ih[2 * HH + jg] + r * (g5 + b_hh[2 * HH + jg]));
        const float hp = h_prev[(size_t)bg * HH + jg];
        const float h  = (1.0f - z) * n + z * hp;
        h_out[(size_t)bg * HH + jg] = h;
        const __nv_bfloat16 hi = __float2bfloat16(h);
        hh_out[(size_t)bg * HH + jg] = hi;
        hl_out[(size_t)bg * HH + jg] = __float2bfloat16(h - __bfloat162float(hi));
    }
}

// ---------------------------------------------------------------------------
// Generic fp32 GRU step — used only for t = 0 (x = embed row, h = feat).
// ---------------------------------------------------------------------------
__global__ __launch_bounds__(256) void gru_step_kernel(
    const float* __restrict__ x, int xs,
    const float* __restrict__ h,
    const float* __restrict__ w_ih,
    const float* __restrict__ w_hh,
    const float* __restrict__ b_ih,
    const float* __restrict__ b_hh,
    float* __restrict__ h_out)
{
    __shared__ float sX[32][32];
    __shared__ float sH[32][32];
    __shared__ float sWih[3][32][32];
    __shared__ float sWhh[3][32][32];

    const int tid = threadIdx.x;
    const int tj  = tid & 31;
    const int tb  = tid >> 5;
    const int j0  = blockIdx.x * 32;
    const int b0  = blockIdx.y * 32;

    float acc[4][6];
    #pragma unroll
    for (int i = 0; i < 4; i++)
        #pragma unroll
        for (int g = 0; g < 6; g++) acc[i][g] = 0.0f;

    const int lb  = tid >> 3;
    const int lk4 = (tid & 7) * 4;

    for (int k0 = 0; k0 < HH; k0 += 32) {
        float4 xv4 = *(const float4*)(x + (size_t)(b0 + lb) * (size_t)xs + k0 + lk4);
        *(float4*)&sX[lb][lk4] = xv4;
        float4 hv4 = *(const float4*)(h + (size_t)(b0 + lb) * HH + k0 + lk4);
        *(float4*)&sH[lb][lk4] = hv4;
        #pragma unroll
        for (int g = 0; g < 3; g++) {
            float4 wi = *(const float4*)(w_ih + (size_t)(g * HH + j0 + lb) * HH + k0 + lk4);
            sWih[g][lk4 + 0][lb] = wi.x;
            sWih[g][lk4 + 1][lb] = wi.y;
            sWih[g][lk4 + 2][lb] = wi.z;
            sWih[g][lk4 + 3][lb] = wi.w;
            float4 wh = *(const float4*)(w_hh + (size_t)(g * HH + j0 + lb) * HH + k0 + lk4);
            sWhh[g][lk4 + 0][lb] = wh.x;
            sWhh[g][lk4 + 1][lb] = wh.y;
            sWhh[g][lk4 + 2][lb] = wh.z;
            sWhh[g][lk4 + 3][lb] = wh.w;
        }
        __syncthreads();

        #pragma unroll
        for (int kk = 0; kk < 32; kk++) {
            const float wi0 = sWih[0][kk][tj];
            const float wi1 = sWih[1][kk][tj];
            const float wi2 = sWih[2][kk][tj];
            const float wh0 = sWhh[0][kk][tj];
            const float wh1 = sWhh[1][kk][tj];
            const float wh2 = sWhh[2][kk][tj];
            #pragma unroll
            for (int i = 0; i < 4; i++) {
                const float xv = sX[tb * 4 + i][kk];
                const float hv = sH[tb * 4 + i][kk];
                acc[i][0] += xv * wi0;
                acc[i][1] += xv * wi1;
                acc[i][2] += xv * wi2;
                acc[i][3] += hv * wh0;
                acc[i][4] += hv * wh1;
                acc[i][5] += hv * wh2;
            }
        }
        __syncthreads();
    }

    const int j = j0 + tj;
    const float bir  = b_ih[j],          bhr = b_hh[j];
    const float biz  = b_ih[HH + j],     bhz = b_hh[HH + j];
    const float bin_ = b_ih[2 * HH + j], bhn = b_hh[2 * HH + j];
    #pragma unroll
    for (int i = 0; i < 4; i++) {
        const int b = b0 + tb * 4 + i;
        const float r = sigmoidf_(acc[i][0] + bir + acc[i][3] + bhr);
        const float z = sigmoidf_(acc[i][1] + biz + acc[i][4] + bhz);
        const float n = tanhf(acc[i][2] + bin_ + r * (acc[i][5] + bhn));
        const float hp = h[(size_t)b * HH + j];
        h_out[(size_t)b * HH + j] = (1.0f - z) * n + z * hp;
    }
}

// ---------------------------------------------------------------------------
// Projection: out[b][v][t] = hist[t][b][:] . proj_w[v][:] + proj_b[v]
// ---------------------------------------------------------------------------
__global__ __launch_bounds__(512) void proj_kernel(
    const float* __restrict__ proj_w,
    const float* __restrict__ proj_b,
    float* __restrict__ out)
{
    __shared__ float sH[TT][33];
    __shared__ float sW[VV][33];

    const int b   = blockIdx.x;
    const int tid = threadIdx.x;
    const int tg  = tid % 25;
    const int vg  = tid / 25;
    const bool active = (tid < 500);

    float acc[8][5];
    #pragma unroll
    for (int i = 0; i < 8; i++)
        #pragma unroll
        for (int jv = 0; jv < 5; jv++) acc[i][jv] = 0.0f;

    for (int k0 = 0; k0 < HH; k0 += 32) {
        for (int idx = tid; idx < TT * 32; idx += 512) {
            const int t = idx >> 5, k = idx & 31;
            sH[t][k] = g_hist[((size_t)t * BB + b) * HH + k0 + k];
        }
        for (int idx = tid; idx < VV * 32; idx += 512) {
            const int v = idx >> 5, k = idx & 31;
            sW[v][k] = proj_w[(size_t)v * HH + k0 + k];
        }
        __syncthreads();

        if (active) {
            #pragma unroll
            for (int kk = 0; kk < 32; kk++) {
                float wv[5];
                #pragma unroll
                for (int jv = 0; jv < 5; jv++) wv[jv] = sW[vg * 5 + jv][kk];
                #pragma unroll
                for (int i = 0; i < 8; i++) {
                    const float hv = sH[tg + 25 * i][kk];
                    #pragma unroll
                    for (int jv = 0; jv < 5; jv++) acc[i][jv] += hv * wv[jv];
                }
            }
        }
        __syncthreads();
    }

    if (active) {
        float pb[5];
        #pragma unroll
        for (int jv = 0; jv < 5; jv++) pb[jv] = proj_b[vg * 5 + jv];
        #pragma unroll
        for (int i = 0; i < 8; i++) {
            const int t = tg + 25 * i;
            #pragma unroll
            for (int jv = 0; jv < 5; jv++) {
                const int v = vg * 5 + jv;
                out[((size_t)b * VV + v) * TT + t] = acc[i][jv] + pb[jv];
            }
        }
    }
}

// ---------------------------------------------------------------------------
extern "C" void kernel_launch(void* const* d_in, const int* in_sizes, int n_in,
                              void* d_out, int out_size)
{
    (void)in_sizes; (void)n_in; (void)out_size;
    const float* feat   = (const float*)d_in[0];
    const float* embed  = (const float*)d_in[1];
    const float* w_ih   = (const float*)d_in[2];
    const float* w_hh   = (const float*)d_in[3];
    const float* b_ih   = (const float*)d_in[4];
    const float* b_hh   = (const float*)d_in[5];
    const float* proj_w = (const float*)d_in[6];
    const float* proj_b = (const float*)d_in[7];
    float* out = (float*)d_out;

    float* hist = nullptr;
    cudaGetSymbolAddress((void**)&hist, g_hist);
    __nv_bfloat16* hhp = nullptr;
    cudaGetSymbolAddress((void**)&hhp, g_hh);
    __nv_bfloat16* hlp = nullptr;
    cudaGetSymbolAddress((void**)&hlp, g_hl);

    cudaFuncSetAttribute(gru_step_mma,
                         cudaFuncAttributeMaxDynamicSharedMemorySize, SMEM_BYTES);

    // one-time weight split/pack (re-run each launch for determinism; cheap)
    prep_weights<<<(6 * HH * HH + 255) / 256, 256>>>(w_ih, w_hh);

    // step 0: x = embed[SOS=0] broadcast, h = feat  -> hist[0]
    gru_step_kernel<<<dim3(HH / 32, BB / 32), 256>>>(embed, 0, feat,
                                                     w_ih, w_hh, b_ih, b_hh, hist);
    convert_h<<<(BB * HH + 255) / 256, 256>>>(hist, hhp, hlp);   // -> pp slot 0

    // steps 1..199: tensor-core fused step
    const dim3 grid_mma(HH / 16, BB / 64);   // (32, 4) = 128 blocks
    for (int t = 1; t < TT; t++) {
        const float* hprev = hist + (size_t)(t - 1) * BB * HH;
        const int pi = (t - 1) & 1, po = t & 1;
        gru_step_mma<<<grid_mma, 256, SMEM_BYTES>>>(
            hprev,
            hhp + (size_t)pi * BB * HH, hlp + (size_t)pi * BB * HH,
            b_ih, b_hh,
            hist + (size_t)t * BB * HH,
            hhp + (size_t)po * BB * HH, hlp + (size_t)po * BB * HH);
    }

    proj_kernel<<<BB, 512>>>(proj_w, proj_b, out);
}

// round 6
// speedup vs baseline: 3.6339x; 1.0765x over previous
#include <cuda_runtime.h>
#include <cuda_bf16.h>
#include <stdint.h>
#include <math.h>

#define BB 256     // batch
#define HH 512     // hidden
#define VV 100     // vocab
#define TT 200     // steps

// fp32 hidden-state history (proj + epilogue need fp32 h)
__device__ float g_hist[(size_t)TT * BB * HH];
// bf16 hi/lo ping-pong of previous hidden state
__device__ __nv_bfloat16 g_hh[2][BB * HH];
__device__ __nv_bfloat16 g_hl[2][BB * HH];
// packed weights: row n = jb*96 + g*16 + j  (jb=0..31, g=0..5, j=0..15), k=0..511
__device__ __nv_bfloat16 g_wh[6 * HH * HH];
__device__ __nv_bfloat16 g_wl[6 * HH * HH];
// global step barrier counter
__device__ unsigned int g_ctr;

__device__ __forceinline__ float sigmoidf_(float x) {
    return 1.0f / (1.0f + expf(-x));
}

// ---------------------------------------------------------------------------
// async / mma helpers
// ---------------------------------------------------------------------------
__device__ __forceinline__ void cp_async16(void* smem_dst, const void* gmem_src) {
    unsigned int s = (unsigned int)__cvta_generic_to_shared(smem_dst);
    asm volatile("cp.async.cg.shared.global [%0], [%1], 16;\n" :: "r"(s), "l"(gmem_src));
}
#define CP_COMMIT() asm volatile("cp.async.commit_group;\n" ::: "memory")
#define CP_WAIT(n)  asm volatile("cp.async.wait_group %0;\n" :: "n"(n) : "memory")

__device__ __forceinline__ void ldsm4(uint32_t r[4], const void* p) {
    unsigned int s = (unsigned int)__cvta_generic_to_shared(p);
    asm volatile("ldmatrix.sync.aligned.m8n8.x4.shared.b16 {%0,%1,%2,%3}, [%4];"
                 : "=r"(r[0]), "=r"(r[1]), "=r"(r[2]), "=r"(r[3]) : "r"(s));
}

__device__ __forceinline__ void mma_bf16(float d[4], const uint32_t a[4],
                                         uint32_t b0, uint32_t b1) {
    asm volatile(
        "mma.sync.aligned.m16n8k16.row.col.f32.bf16.bf16.f32 "
        "{%0,%1,%2,%3}, {%4,%5,%6,%7}, {%8,%9}, {%0,%1,%2,%3};"
        : "+f"(d[0]), "+f"(d[1]), "+f"(d[2]), "+f"(d[3])
        : "r"(a[0]), "r"(a[1]), "r"(a[2]), "r"(a[3]), "r"(b0), "r"(b1));
}

// ---------------------------------------------------------------------------
// One-time weight prep: pack + split fp32 -> bf16 hi/lo.
// ---------------------------------------------------------------------------
__global__ __launch_bounds__(256) void prep_weights(
    const float* __restrict__ w_ih, const float* __restrict__ w_hh)
{
    int idx = blockIdx.x * 256 + threadIdx.x;
    if (idx >= 6 * HH * HH) return;
    int n = idx / HH, k = idx % HH;
    int jb = n / 96, rr = n % 96, g = rr / 16, j = rr % 16;
    const float* src = (g < 3) ? w_ih : w_hh;
    float v = src[(size_t)((g % 3) * HH + jb * 16 + j) * HH + k];
    __nv_bfloat16 hi = __float2bfloat16(v);
    g_wh[idx] = hi;
    g_wl[idx] = __float2bfloat16(v - __bfloat162float(hi));
}

__global__ void reset_ctr_kernel() { g_ctr = 0u; }

// ---------------------------------------------------------------------------
// Convert fp32 h -> bf16 hi/lo (after step 0)
// ---------------------------------------------------------------------------
__global__ __launch_bounds__(256) void convert_h(
    const float* __restrict__ h, __nv_bfloat16* __restrict__ hh,
    __nv_bfloat16* __restrict__ hl)
{
    int idx = blockIdx.x * 256 + threadIdx.x;
    if (idx >= BB * HH) return;
    float v = h[idx];
    __nv_bfloat16 hi = __float2bfloat16(v);
    hh[idx] = hi;
    hl[idx] = __float2bfloat16(v - __bfloat162float(hi));
}

// ---------------------------------------------------------------------------
// Persistent tensor-core GRU: all steps t=1..199 in one kernel.
// Grid (32 jb, 4 bq) = 128 blocks (one wave, 1 block/SM), 256 threads.
// B weight tile (96x512 hi+lo) resident in smem for the whole kernel.
// A (h hi/lo) streamed per step via cp.async, k=32 double buffer.
// Global barrier between steps via monotonic atomic counter.
// ---------------------------------------------------------------------------
#define RS_B   520                 // B row stride (bf16): 1040B, conflict-free
#define RS_A   40                  // A row stride (bf16): 80B, conflict-free
#define SA_MAT (64 * RS_A)         // 2560 bf16
#define SA_BUF (2 * SA_MAT)        // hi+lo per buffer
#define OFF_BH 0
#define OFF_BL (96 * RS_B)
#define OFF_A  (2 * 96 * RS_B)
#define SMEM_P ((2 * 96 * RS_B + 2 * SA_BUF) * 2)   // 220160 bytes

__global__ __launch_bounds__(256) void gru_persistent(
    const float* __restrict__ b_ih,
    const float* __restrict__ b_hh,
    float* __restrict__ hist,                 // [TT][BB][HH]
    __nv_bfloat16* __restrict__ hh_base,      // [2][BB*HH]
    __nv_bfloat16* __restrict__ hl_base)
{
    extern __shared__ __align__(16) __nv_bfloat16 dsm[];

    const int tid  = threadIdx.x;
    const int lane = tid & 31;
    const int w    = tid >> 5;
    const int mw   = w & 3;
    const int nv   = w >> 2;
    const int jb   = blockIdx.x;         // 0..31
    const int b0   = blockIdx.y * 64;    // batch base

    // ---- load resident B tile (hi+lo) ----
    for (int i = tid; i < 96 * 64; i += 256) {          // 64 f4 per row
        const int row = i >> 6;
        const int c8  = (i & 63) * 8;
        const size_t gsrc = (size_t)(jb * 96 + row) * HH + c8;
        cp_async16(dsm + OFF_BH + row * RS_B + c8, g_wh + gsrc);
        cp_async16(dsm + OFF_BL + row * RS_B + c8, g_wl + gsrc);
    }
    CP_COMMIT();

    // ---- per-thread A cp.async invariants (2 f4/thread/chunk) ----
    int a_mat[2], a_rowL[2], a_c8[2];
    #pragma unroll
    for (int n2 = 0; n2 < 2; n2++) {
        const int f = tid + 256 * n2;   // 0..511
        a_mat[n2]  = f >> 8;
        a_rowL[n2] = (f >> 2) & 63;
        a_c8[n2]   = (f & 3) * 8;
    }

    // ---- ldmatrix lane offsets ----
    const int a_row  = mw * 16 + (lane & 15);
    const int a_koff = (lane >> 4) * 8;
    const int b_rowL = (lane & 7) + ((lane & 16) ? 8 : 0);
    const int b_koff = (lane & 8) ? 8 : 0;
    const int r_base = mw * 16 + (lane >> 2);

    // ---- epilogue register state (nv==0 threads own (b,j) outputs) ----
    float hp[2][4];
    float br_[4], bz_[4], bni_[4], bnh_[4];
    if (nv == 0) {
        #pragma unroll
        for (int ji = 0; ji < 4; ji++) {
            const int jloc = (ji >> 1) * 8 + (lane & 3) * 2 + (ji & 1);
            const int jg   = jb * 16 + jloc;
            br_[ji]  = b_ih[jg] + b_hh[jg];
            bz_[ji]  = b_ih[HH + jg] + b_hh[HH + jg];
            bni_[ji] = b_ih[2 * HH + jg];
            bnh_[ji] = b_hh[2 * HH + jg];
            #pragma unroll
            for (int ri = 0; ri < 2; ri++)
                hp[ri][ji] = hist[(size_t)(b0 + r_base + ri * 8) * HH + jg];
        }
    }

    CP_WAIT(0);
    __syncthreads();

    float acc[6][4];
    #pragma unroll
    for (int f = 0; f < 6; f++)
        #pragma unroll
        for (int i = 0; i < 4; i++) acc[f][i] = 0.0f;

    for (int t = 1; t < TT; t++) {
        const __nv_bfloat16* srcH = hh_base + (size_t)((t - 1) & 1) * BB * HH;
        const __nv_bfloat16* srcL = hl_base + (size_t)((t - 1) & 1) * BB * HH;

        // prologue: chunk 0 -> buf 0
        #pragma unroll
        for (int n2 = 0; n2 < 2; n2++) {
            const __nv_bfloat16* s =
                (a_mat[n2] ? srcL : srcH) + (size_t)(b0 + a_rowL[n2]) * HH + a_c8[n2];
            cp_async16(dsm + OFF_A + a_mat[n2] * SA_MAT + a_rowL[n2] * RS_A + a_c8[n2], s);
        }
        CP_COMMIT();

        const int NCH = HH / 32;   // 16
        for (int c = 0; c < NCH; c++) {
            if (c + 1 < NCH) {
                const int nb = (c + 1) & 1;
                const int k0 = (c + 1) * 32;
                #pragma unroll
                for (int n2 = 0; n2 < 2; n2++) {
                    const __nv_bfloat16* s = (a_mat[n2] ? srcL : srcH)
                        + (size_t)(b0 + a_rowL[n2]) * HH + k0 + a_c8[n2];
                    cp_async16(dsm + OFF_A + nb * SA_BUF + a_mat[n2] * SA_MAT
                               + a_rowL[n2] * RS_A + a_c8[n2], s);
                }
                CP_COMMIT();
                CP_WAIT(1);
            } else {
                CP_WAIT(0);
            }
            __syncthreads();

            const __nv_bfloat16* bufA = dsm + OFF_A + (c & 1) * SA_BUF;
            #pragma unroll
            for (int q = 0; q < 2; q++) {
                uint32_t aH[4], aL[4];
                ldsm4(aH, bufA + a_row * RS_A + q * 16 + a_koff);
                ldsm4(aL, bufA + SA_MAT + a_row * RS_A + q * 16 + a_koff);
                const int kg = c * 32 + q * 16 + b_koff;
                #pragma unroll
                for (int p = 0; p < 3; p++) {
                    const int brow = nv * 48 + p * 16 + b_rowL;
                    uint32_t bh[4], bl[4];
                    ldsm4(bh, dsm + OFF_BH + brow * RS_B + kg);
                    ldsm4(bl, dsm + OFF_BL + brow * RS_B + kg);
                    mma_bf16(acc[2 * p],     aH, bh[0], bh[1]);
                    mma_bf16(acc[2 * p],     aH, bl[0], bl[1]);
                    mma_bf16(acc[2 * p],     aL, bh[0], bh[1]);
                    mma_bf16(acc[2 * p + 1], aH, bh[2], bh[3]);
                    mma_bf16(acc[2 * p + 1], aH, bl[2], bl[3]);
                    mma_bf16(acc[2 * p + 1], aL, bh[2], bh[3]);
                }
            }
            __syncthreads();
        }

        // ---- epilogue: exchange hh-gates via smem (aliases A buffers) ----
        float* sE = (float*)(dsm + OFF_A);
        if (nv == 1) {
            #pragma unroll
            for (int f = 0; f < 6; f++) {
                const int cb = f * 8 + (lane & 3) * 2;
                sE[r_base * 52 + cb]           = acc[f][0];
                sE[r_base * 52 + cb + 1]       = acc[f][1];
                sE[(r_base + 8) * 52 + cb]     = acc[f][2];
                sE[(r_base + 8) * 52 + cb + 1] = acc[f][3];
            }
        }
        __syncthreads();

        if (nv == 0) {
            __nv_bfloat16* dstH = hh_base + (size_t)(t & 1) * BB * HH;
            __nv_bfloat16* dstL = hl_base + (size_t)(t & 1) * BB * HH;
            float* hout = hist + (size_t)t * BB * HH;
            #pragma unroll
            for (int ri = 0; ri < 2; ri++) {
                const int row = r_base + ri * 8;
                const int bg  = b0 + row;
                #pragma unroll
                for (int ji = 0; ji < 4; ji++) {
                    const int jloc = (ji >> 1) * 8 + (lane & 3) * 2 + (ji & 1);
                    const int fo   = ji >> 1;
                    const int ii   = (ri << 1) | (ji & 1);
                    const float gr = acc[0 + fo][ii];
                    const float gz = acc[2 + fo][ii];
                    const float gn = acc[4 + fo][ii];
                    const float hr = sE[row * 52 +      jloc];
                    const float hz = sE[row * 52 + 16 + jloc];
                    const float hn = sE[row * 52 + 32 + jloc];
                    const float rv = sigmoidf_(gr + hr + br_[ji]);
                    const float zv = sigmoidf_(gz + hz + bz_[ji]);
                    const float nn = tanhf(gn + bni_[ji] + rv * (hn + bnh_[ji]));
                    const float hv = (1.0f - zv) * nn + zv * hp[ri][ji];
                    hp[ri][ji] = hv;
                    const int jg = jb * 16 + jloc;
                    hout[(size_t)bg * HH + jg] = hv;
                    const __nv_bfloat16 hi = __float2bfloat16(hv);
                    dstH[(size_t)bg * HH + jg] = hi;
                    dstL[(size_t)bg * HH + jg] =
                        __float2bfloat16(hv - __bfloat162float(hi));
                }
            }
            __threadfence();
        }

        // reset accumulators
        #pragma unroll
        for (int f = 0; f < 6; f++)
            #pragma unroll
            for (int i = 0; i < 4; i++) acc[f][i] = 0.0f;

        __syncthreads();

        // ---- grid barrier (skip after final step) ----
        if (t < TT - 1) {
            if (tid == 0) {
                atomicAdd(&g_ctr, 1u);
                const unsigned int target = (unsigned int)t * 128u;
                unsigned int v;
                do {
                    asm volatile("ld.acquire.gpu.u32 %0, [%1];"
                                 : "=r"(v) : "l"(&g_ctr));
                } while (v < target);
            }
            __syncthreads();
        }
    }
}

// ---------------------------------------------------------------------------
// Generic fp32 GRU step — used only for t = 0 (x = embed row, h = feat).
// ---------------------------------------------------------------------------
__global__ __launch_bounds__(256) void gru_step_kernel(
    const float* __restrict__ x, int xs,
    const float* __restrict__ h,
    const float* __restrict__ w_ih,
    const float* __restrict__ w_hh,
    const float* __restrict__ b_ih,
    const float* __restrict__ b_hh,
    float* __restrict__ h_out)
{
    __shared__ float sX[32][32];
    __shared__ float sH[32][32];
    __shared__ float sWih[3][32][32];
    __shared__ float sWhh[3][32][32];

    const int tid = threadIdx.x;
    const int tj  = tid & 31;
    const int tb  = tid >> 5;
    const int j0  = blockIdx.x * 32;
    const int b0  = blockIdx.y * 32;

    float acc[4][6];
    #pragma unroll
    for (int i = 0; i < 4; i++)
        #pragma unroll
        for (int g = 0; g < 6; g++) acc[i][g] = 0.0f;

    const int lb  = tid >> 3;
    const int lk4 = (tid & 7) * 4;

    for (int k0 = 0; k0 < HH; k0 += 32) {
        float4 xv4 = *(const float4*)(x + (size_t)(b0 + lb) * (size_t)xs + k0 + lk4);
        *(float4*)&sX[lb][lk4] = xv4;
        float4 hv4 = *(const float4*)(h + (size_t)(b0 + lb) * HH + k0 + lk4);
        *(float4*)&sH[lb][lk4] = hv4;
        #pragma unroll
        for (int g = 0; g < 3; g++) {
            float4 wi = *(const float4*)(w_ih + (size_t)(g * HH + j0 + lb) * HH + k0 + lk4);
            sWih[g][lk4 + 0][lb] = wi.x;
            sWih[g][lk4 + 1][lb] = wi.y;
            sWih[g][lk4 + 2][lb] = wi.z;
            sWih[g][lk4 + 3][lb] = wi.w;
            float4 wh = *(const float4*)(w_hh + (size_t)(g * HH + j0 + lb) * HH + k0 + lk4);
            sWhh[g][lk4 + 0][lb] = wh.x;
            sWhh[g][lk4 + 1][lb] = wh.y;
            sWhh[g][lk4 + 2][lb] = wh.z;
            sWhh[g][lk4 + 3][lb] = wh.w;
        }
        __syncthreads();

        #pragma unroll
        for (int kk = 0; kk < 32; kk++) {
            const float wi0 = sWih[0][kk][tj];
            const float wi1 = sWih[1][kk][tj];
            const float wi2 = sWih[2][kk][tj];
            const float wh0 = sWhh[0][kk][tj];
            const float wh1 = sWhh[1][kk][tj];
            const float wh2 = sWhh[2][kk][tj];
            #pragma unroll
            for (int i = 0; i < 4; i++) {
                const float xv = sX[tb * 4 + i][kk];
                const float hv = sH[tb * 4 + i][kk];
                acc[i][0] += xv * wi0;
                acc[i][1] += xv * wi1;
                acc[i][2] += xv * wi2;
                acc[i][3] += hv * wh0;
                acc[i][4] += hv * wh1;
                acc[i][5] += hv * wh2;
            }
        }
        __syncthreads();
    }

    const int j = j0 + tj;
    const float bir  = b_ih[j],          bhr = b_hh[j];
    const float biz  = b_ih[HH + j],     bhz = b_hh[HH + j];
    const float bin_ = b_ih[2 * HH + j], bhn = b_hh[2 * HH + j];
    #pragma unroll
    for (int i = 0; i < 4; i++) {
        const int b = b0 + tb * 4 + i;
        const float r = sigmoidf_(acc[i][0] + bir + acc[i][3] + bhr);
        const float z = sigmoidf_(acc[i][1] + biz + acc[i][4] + bhz);
        const float n = tanhf(acc[i][2] + bin_ + r * (acc[i][5] + bhn));
        const float hp = h[(size_t)b * HH + j];
        h_out[(size_t)b * HH + j] = (1.0f - z) * n + z * hp;
    }
}

// ---------------------------------------------------------------------------
// Projection: out[b][v][t] = hist[t][b][:] . proj_w[v][:] + proj_b[v]
// ---------------------------------------------------------------------------
__global__ __launch_bounds__(512) void proj_kernel(
    const float* __restrict__ proj_w,
    const float* __restrict__ proj_b,
    float* __restrict__ out)
{
    __shared__ float sH[TT][33];
    __shared__ float sW[VV][33];

    const int b   = blockIdx.x;
    const int tid = threadIdx.x;
    const int tg  = tid % 25;
    const int vg  = tid / 25;
    const bool active = (tid < 500);

    float acc[8][5];
    #pragma unroll
    for (int i = 0; i < 8; i++)
        #pragma unroll
        for (int jv = 0; jv < 5; jv++) acc[i][jv] = 0.0f;

    for (int k0 = 0; k0 < HH; k0 += 32) {
        for (int idx = tid; idx < TT * 32; idx += 512) {
            const int t = idx >> 5, k = idx & 31;
            sH[t][k] = g_hist[((size_t)t * BB + b) * HH + k0 + k];
        }
        for (int idx = tid; idx < VV * 32; idx += 512) {
            const int v = idx >> 5, k = idx & 31;
            sW[v][k] = proj_w[(size_t)v * HH + k0 + k];
        }
        __syncthreads();

        if (active) {
            #pragma unroll
            for (int kk = 0; kk < 32; kk++) {
                float wv[5];
                #pragma unroll
                for (int jv = 0; jv < 5; jv++) wv[jv] = sW[vg * 5 + jv][kk];
                #pragma unroll
                for (int i = 0; i < 8; i++) {
                    const float hv = sH[tg + 25 * i][kk];
                    #pragma unroll
                    for (int jv = 0; jv < 5; jv++) acc[i][jv] += hv * wv[jv];
                }
            }
        }
        __syncthreads();
    }

    if (active) {
        float pb[5];
        #pragma unroll
        for (int jv = 0; jv < 5; jv++) pb[jv] = proj_b[vg * 5 + jv];
        #pragma unroll
        for (int i = 0; i < 8; i++) {
            const int t = tg + 25 * i;
            #pragma unroll
            for (int jv = 0; jv < 5; jv++) {
                const int v = vg * 5 + jv;
                out[((size_t)b * VV + v) * TT + t] = acc[i][jv] + pb[jv];
            }
        }
    }
}

// ---------------------------------------------------------------------------
extern "C" void kernel_launch(void* const* d_in, const int* in_sizes, int n_in,
                              void* d_out, int out_size)
{
    (void)in_sizes; (void)n_in; (void)out_size;
    const float* feat   = (const float*)d_in[0];
    const float* embed  = (const float*)d_in[1];
    const float* w_ih   = (const float*)d_in[2];
    const float* w_hh   = (const float*)d_in[3];
    const float* b_ih   = (const float*)d_in[4];
    const float* b_hh   = (const float*)d_in[5];
    const float* proj_w = (const float*)d_in[6];
    const float* proj_b = (const float*)d_in[7];
    float* out = (float*)d_out;

    float* hist = nullptr;
    cudaGetSymbolAddress((void**)&hist, g_hist);
    __nv_bfloat16* hhp = nullptr;
    cudaGetSymbolAddress((void**)&hhp, g_hh);
    __nv_bfloat16* hlp = nullptr;
    cudaGetSymbolAddress((void**)&hlp, g_hl);

    cudaFuncSetAttribute(gru_persistent,
                         cudaFuncAttributeMaxDynamicSharedMemorySize, SMEM_P);

    prep_weights<<<(6 * HH * HH + 255) / 256, 256>>>(w_ih, w_hh);
    reset_ctr_kernel<<<1, 1>>>();

    // step 0: x = embed[SOS=0] broadcast, h = feat  -> hist[0]
    gru_step_kernel<<<dim3(HH / 32, BB / 32), 256>>>(embed, 0, feat,
                                                     w_ih, w_hh, b_ih, b_hh, hist);
    convert_h<<<(BB * HH + 255) / 256, 256>>>(hist, hhp, hlp);   // -> pp slot 0

    // steps 1..199: persistent tensor-core kernel (one wave of 128 blocks)
    gru_persistent<<<dim3(32, 4), 256, SMEM_P>>>(b_ih, b_hh, hist, hhp, hlp);

    proj_kernel<<<BB, 512>>>(proj_w, proj_b, out);
}

// round 7
// speedup vs baseline: 4.3699x; 1.2026x over previous
#include <cuda_runtime.h>
#include <cuda_bf16.h>
#include <stdint.h>
#include <math.h>

#define BB 256     // batch
#define HH 512     // hidden
#define VV 100     // vocab
#define TT 200     // steps

// fp32 hidden-state history (proj + epilogue need fp32 h)
__device__ float g_hist[(size_t)TT * BB * HH];
// bf16 hi/lo ping-pong of previous hidden state
__device__ __nv_bfloat16 g_hh[2][BB * HH];
__device__ __nv_bfloat16 g_hl[2][BB * HH];
// packed weights: row n = jb*96 + g*16 + j  (jb=0..31, g=0..5, j=0..15), k=0..511
__device__ __nv_bfloat16 g_wh[6 * HH * HH];
__device__ __nv_bfloat16 g_wl[6 * HH * HH];
// per-batch-group step barrier counters
__device__ unsigned int g_ctrs[4];

__device__ __forceinline__ float sigmoidf_(float x) {
    return 1.0f / (1.0f + expf(-x));
}

// ---------------------------------------------------------------------------
// async / mma helpers
// ---------------------------------------------------------------------------
__device__ __forceinline__ void cp_async16(void* smem_dst, const void* gmem_src) {
    unsigned int s = (unsigned int)__cvta_generic_to_shared(smem_dst);
    asm volatile("cp.async.cg.shared.global [%0], [%1], 16;\n" :: "r"(s), "l"(gmem_src));
}
#define CP_COMMIT() asm volatile("cp.async.commit_group;\n" ::: "memory")
#define CP_WAIT(n)  asm volatile("cp.async.wait_group %0;\n" :: "n"(n) : "memory")

__device__ __forceinline__ void ldsm4(uint32_t r[4], const void* p) {
    unsigned int s = (unsigned int)__cvta_generic_to_shared(p);
    asm volatile("ldmatrix.sync.aligned.m8n8.x4.shared.b16 {%0,%1,%2,%3}, [%4];"
                 : "=r"(r[0]), "=r"(r[1]), "=r"(r[2]), "=r"(r[3]) : "r"(s));
}

__device__ __forceinline__ void mma_bf16(float d[4], const uint32_t a[4],
                                         uint32_t b0, uint32_t b1) {
    asm volatile(
        "mma.sync.aligned.m16n8k16.row.col.f32.bf16.bf16.f32 "
        "{%0,%1,%2,%3}, {%4,%5,%6,%7}, {%8,%9}, {%0,%1,%2,%3};"
        : "+f"(d[0]), "+f"(d[1]), "+f"(d[2]), "+f"(d[3])
        : "r"(a[0]), "r"(a[1]), "r"(a[2]), "r"(a[3]), "r"(b0), "r"(b1));
}

// ---------------------------------------------------------------------------
// One-time weight prep: pack + split fp32 -> bf16 hi/lo.
// ---------------------------------------------------------------------------
__global__ __launch_bounds__(256) void prep_weights(
    const float* __restrict__ w_ih, const float* __restrict__ w_hh)
{
    int idx = blockIdx.x * 256 + threadIdx.x;
    if (idx >= 6 * HH * HH) return;
    int n = idx / HH, k = idx % HH;
    int jb = n / 96, rr = n % 96, g = rr / 16, j = rr % 16;
    const float* src = (g < 3) ? w_ih : w_hh;
    float v = src[(size_t)((g % 3) * HH + jb * 16 + j) * HH + k];
    __nv_bfloat16 hi = __float2bfloat16(v);
    g_wh[idx] = hi;
    g_wl[idx] = __float2bfloat16(v - __bfloat162float(hi));
}

__global__ void reset_ctr_kernel() {
    if (threadIdx.x < 4) g_ctrs[threadIdx.x] = 0u;
}

// ---------------------------------------------------------------------------
// Convert fp32 h -> bf16 hi/lo (after step 0)
// ---------------------------------------------------------------------------
__global__ __launch_bounds__(256) void convert_h(
    const float* __restrict__ h, __nv_bfloat16* __restrict__ hh,
    __nv_bfloat16* __restrict__ hl)
{
    int idx = blockIdx.x * 256 + threadIdx.x;
    if (idx >= BB * HH) return;
    float v = h[idx];
    __nv_bfloat16 hi = __float2bfloat16(v);
    hh[idx] = hi;
    hl[idx] = __float2bfloat16(v - __bfloat162float(hi));
}

// ---------------------------------------------------------------------------
// Persistent tensor-core GRU, v2.
// Grid (32 jb, 4 bq) = 128 blocks, 384 threads (12 warps: 4 mw x 3 nv(n=32)).
// B tile (96x512, hi+lo) XOR-swizzled, SMEM-resident whole kernel (196.6 KB).
// A (h hi/lo) streamed per step, k=64 chunks, double buffer, XOR-swizzled.
// Step barrier: per-bq-group atomic counter (fan-in 32).
// ---------------------------------------------------------------------------
#define THR    384
#define B_MATS (96 * 512)                   // bf16 per B matrix (swizzled, no pad)
#define OFF_A  (2 * B_MATS)                 // 98304 bf16
#define A_MATS (64 * 64)                    // bf16 per A matrix per chunk (k=64)
#define A_BUF  (2 * A_MATS)                 // hi+lo per buffer = 8192 bf16
#define SMEM_P ((OFF_A + 2 * A_BUF) * 2)    // 229376 bytes (224 KB)
#define NCH    8                            // K chunks of 64

__global__ __launch_bounds__(THR) void gru_persistent(
    const float* __restrict__ b_ih,
    const float* __restrict__ b_hh,
    float* __restrict__ hist,                 // [TT][BB][HH]
    __nv_bfloat16* __restrict__ hh_base,      // [2][BB*HH]
    __nv_bfloat16* __restrict__ hl_base)
{
    extern __shared__ __align__(16) __nv_bfloat16 dsm[];

    const int tid  = threadIdx.x;
    const int lane = tid & 31;
    const int w    = tid >> 5;           // 0..11
    const int mw   = w & 3;              // m16 tile
    const int nv   = w >> 2;             // 0..2, n=32 each
    const int jb   = blockIdx.x;         // 0..31
    const int bq   = blockIdx.y;         // 0..3
    const int b0   = bq * 64;

    // ================= resident B load (swizzled, once) =================
    for (int i = tid; i < 2 * 96 * 64; i += THR) {     // 16B granules
        const int mat = i / (96 * 64);
        const int rr  = i % (96 * 64);
        const int row = rr >> 6;
        const int g   = rr & 63;
        const int gs  = (g & 56) | ((g ^ row) & 7);
        const __nv_bfloat16* src =
            (mat ? g_wl : g_wh) + (size_t)(jb * 96 + row) * HH + g * 8;
        cp_async16(dsm + mat * B_MATS + row * 512 + gs * 8, src);
    }
    CP_COMMIT();

    // ========== per-thread A-chunk cp.async descriptors (<=3 each) =========
    // per chunk: 2 mats x 64 rows x 8 granules = 1024 granules
    int aMat[3], aDst[3], aSrc[3];
    #pragma unroll
    for (int k = 0; k < 3; k++) {
        const int i = tid + THR * k;
        if (i < 1024) {
            const int mat = i >> 9;
            const int r   = (i >> 3) & 63;
            const int g   = i & 7;
            aMat[k] = mat;
            aDst[k] = mat * A_MATS + r * 64 + ((g ^ (r & 7)) * 8);
            aSrc[k] = (b0 + r) * HH + g * 8;
        }
    }
    const bool a3 = (tid + 2 * THR < 1024);

    // ================= ldmatrix lane invariants =================
    const int a_row  = mw * 16 + (lane & 15);
    const int a_g0   = (lane >> 4);              // 0/1 (k-half granule)
    const int a_base = a_row * 64;
    const int a_r7   = a_row & 7;
    const int b_rowL = (lane & 7) + ((lane & 16) ? 8 : 0);
    const int b_g0   = (lane & 8) ? 1 : 0;       // k-half granule
    int b_base[2], b_r7[2];
    #pragma unroll
    for (int p = 0; p < 2; p++) {
        const int brow = nv * 32 + p * 16 + b_rowL;
        b_base[p] = brow * 512;
        b_r7[p]   = brow & 7;
    }
    const int r_base = mw * 16 + (lane >> 2);

    // ================= epilogue per-thread state =================
    // outputs e = tid, tid+384, tid+768 (<1024): (b = e>>4, j = e&15)
    float hp[3], br_[3], bz_[3], bni_[3], bnh_[3];
    int   ooff[3];
    #pragma unroll
    for (int n = 0; n < 3; n++) {
        const int e = tid + THR * n;
        if (e < 1024) {
            const int b  = e >> 4;
            const int j  = e & 15;
            const int jg = jb * 16 + j;
            ooff[n] = (b0 + b) * HH + jg;
            br_[n]  = b_ih[jg] + b_hh[jg];
            bz_[n]  = b_ih[HH + jg] + b_hh[HH + jg];
            bni_[n] = b_ih[2 * HH + jg];
            bnh_[n] = b_hh[2 * HH + jg];
            hp[n]   = hist[ooff[n]];
        }
    }

    CP_WAIT(0);
    __syncthreads();

    float acc[4][4];
    #pragma unroll
    for (int f = 0; f < 4; f++)
        #pragma unroll
        for (int i = 0; i < 4; i++) acc[f][i] = 0.0f;

    float* sG = (float*)(dsm + OFF_A);   // [64][100] gate exchange (aliases A)

    for (int t = 1; t < TT; t++) {
        const __nv_bfloat16* srcH = hh_base + (size_t)((t - 1) & 1) * BB * HH;
        const __nv_bfloat16* srcL = hl_base + (size_t)((t - 1) & 1) * BB * HH;

        // prologue: chunk 0 -> buf 0
        {
            __nv_bfloat16* buf = dsm + OFF_A;
            cp_async16(buf + aDst[0], (aMat[0] ? srcL : srcH) + aSrc[0]);
            cp_async16(buf + aDst[1], (aMat[1] ? srcL : srcH) + aSrc[1]);
            if (a3)
                cp_async16(buf + aDst[2], (aMat[2] ? srcL : srcH) + aSrc[2]);
            CP_COMMIT();
        }

        #pragma unroll 1
        for (int c = 0; c < NCH; c++) {
            if (c + 1 < NCH) {
                __nv_bfloat16* buf = dsm + OFF_A + ((c + 1) & 1) * A_BUF;
                const int k0 = (c + 1) * 64;
                cp_async16(buf + aDst[0], (aMat[0] ? srcL : srcH) + aSrc[0] + k0);
                cp_async16(buf + aDst[1], (aMat[1] ? srcL : srcH) + aSrc[1] + k0);
                if (a3)
                    cp_async16(buf + aDst[2], (aMat[2] ? srcL : srcH) + aSrc[2] + k0);
                CP_COMMIT();
                CP_WAIT(1);
            } else {
                CP_WAIT(0);
            }
            __syncthreads();

            const __nv_bfloat16* bufA = dsm + OFF_A + (c & 1) * A_BUF;
            #pragma unroll
            for (int q = 0; q < 4; q++) {
                uint32_t aH[4], aL[4];
                const int gsA = ((2 * q + a_g0) ^ a_r7) * 8;
                ldsm4(aH, bufA + a_base + gsA);
                ldsm4(aL, bufA + A_MATS + a_base + gsA);
                const int gqB = c * 8 + 2 * q + b_g0;
                #pragma unroll
                for (int p = 0; p < 2; p++) {
                    const int gsB = (gqB & 56) | ((gqB ^ b_r7[p]) & 7);
                    const int off = b_base[p] + gsB * 8;
                    uint32_t bh[4], bl[4];
                    ldsm4(bh, dsm + off);
                    ldsm4(bl, dsm + B_MATS + off);
                    mma_bf16(acc[2 * p],     aH, bh[0], bh[1]);
                    mma_bf16(acc[2 * p],     aH, bl[0], bl[1]);
                    mma_bf16(acc[2 * p],     aL, bh[0], bh[1]);
                    mma_bf16(acc[2 * p + 1], aH, bh[2], bh[3]);
                    mma_bf16(acc[2 * p + 1], aH, bl[2], bl[3]);
                    mma_bf16(acc[2 * p + 1], aL, bh[2], bh[3]);
                }
            }
            __syncthreads();   // buffer consumed (and pre-sG for last chunk)
        }

        // ---- write fragments to sG[64][100] ----
        {
            #pragma unroll
            for (int f = 0; f < 4; f++) {
                const int cb = nv * 32 + f * 8 + (lane & 3) * 2;
                sG[r_base * 100 + cb]           = acc[f][0];
                sG[r_base * 100 + cb + 1]       = acc[f][1];
                sG[(r_base + 8) * 100 + cb]     = acc[f][2];
                sG[(r_base + 8) * 100 + cb + 1] = acc[f][3];
            }
        }
        __syncthreads();

        // ---- gate epilogue ----
        {
            __nv_bfloat16* dstH = hh_base + (size_t)(t & 1) * BB * HH;
            __nv_bfloat16* dstL = hl_base + (size_t)(t & 1) * BB * HH;
            float* hout = hist + (size_t)t * BB * HH;
            #pragma unroll
            for (int n = 0; n < 3; n++) {
                const int e = tid + THR * n;
                if (e < 1024) {
                    const int b = e >> 4, j = e & 15;
                    const float gr = sG[b * 100 + j];
                    const float gz = sG[b * 100 + 16 + j];
                    const float gn = sG[b * 100 + 32 + j];
                    const float hr = sG[b * 100 + 48 + j];
                    const float hz = sG[b * 100 + 64 + j];
                    const float hn = sG[b * 100 + 80 + j];
                    const float rv = sigmoidf_(gr + hr + br_[n]);
                    const float zv = sigmoidf_(gz + hz + bz_[n]);
                    const float nn = tanhf(gn + bni_[n] + rv * (hn + bnh_[n]));
                    const float hv = (1.0f - zv) * nn + zv * hp[n];
                    hp[n] = hv;
                    hout[ooff[n]] = hv;
                    const __nv_bfloat16 hi = __float2bfloat16(hv);
                    dstH[ooff[n]] = hi;
                    dstL[ooff[n]] = __float2bfloat16(hv - __bfloat162float(hi));
                }
            }
        }
        __threadfence();

        // reset accumulators
        #pragma unroll
        for (int f = 0; f < 4; f++)
            #pragma unroll
            for (int i = 0; i < 4; i++) acc[f][i] = 0.0f;

        __syncthreads();

        // ---- per-group grid barrier (skip after final step) ----
        if (t < TT - 1) {
            if (tid == 0) {
                atomicAdd(&g_ctrs[bq], 1u);
                const unsigned int target = (unsigned int)t * 32u;
                unsigned int v;
                do {
                    asm volatile("ld.acquire.gpu.u32 %0, [%1];"
                                 : "=r"(v) : "l"(&g_ctrs[bq]));
                } while (v < target);
            }
            __syncthreads();
        }
    }
}

// ---------------------------------------------------------------------------
// Generic fp32 GRU step — used only for t = 0 (x = embed row, h = feat).
// ---------------------------------------------------------------------------
__global__ __launch_bounds__(256) void gru_step_kernel(
    const float* __restrict__ x, int xs,
    const float* __restrict__ h,
    const float* __restrict__ w_ih,
    const float* __restrict__ w_hh,
    const float* __restrict__ b_ih,
    const float* __restrict__ b_hh,
    float* __restrict__ h_out)
{
    __shared__ float sX[32][32];
    __shared__ float sH[32][32];
    __shared__ float sWih[3][32][32];
    __shared__ float sWhh[3][32][32];

    const int tid = threadIdx.x;
    const int tj  = tid & 31;
    const int tb  = tid >> 5;
    const int j0  = blockIdx.x * 32;
    const int b0  = blockIdx.y * 32;

    float acc[4][6];
    #pragma unroll
    for (int i = 0; i < 4; i++)
        #pragma unroll
        for (int g = 0; g < 6; g++) acc[i][g] = 0.0f;

    const int lb  = tid >> 3;
    const int lk4 = (tid & 7) * 4;

    for (int k0 = 0; k0 < HH; k0 += 32) {
        float4 xv4 = *(const float4*)(x + (size_t)(b0 + lb) * (size_t)xs + k0 + lk4);
        *(float4*)&sX[lb][lk4] = xv4;
        float4 hv4 = *(const float4*)(h + (size_t)(b0 + lb) * HH + k0 + lk4);
        *(float4*)&sH[lb][lk4] = hv4;
        #pragma unroll
        for (int g = 0; g < 3; g++) {
            float4 wi = *(const float4*)(w_ih + (size_t)(g * HH + j0 + lb) * HH + k0 + lk4);
            sWih[g][lk4 + 0][lb] = wi.x;
            sWih[g][lk4 + 1][lb] = wi.y;
            sWih[g][lk4 + 2][lb] = wi.z;
            sWih[g][lk4 + 3][lb] = wi.w;
            float4 wh = *(const float4*)(w_hh + (size_t)(g * HH + j0 + lb) * HH + k0 + lk4);
            sWhh[g][lk4 + 0][lb] = wh.x;
            sWhh[g][lk4 + 1][lb] = wh.y;
            sWhh[g][lk4 + 2][lb] = wh.z;
            sWhh[g][lk4 + 3][lb] = wh.w;
        }
        __syncthreads();

        #pragma unroll
        for (int kk = 0; kk < 32; kk++) {
            const float wi0 = sWih[0][kk][tj];
            const float wi1 = sWih[1][kk][tj];
            const float wi2 = sWih[2][kk][tj];
            const float wh0 = sWhh[0][kk][tj];
            const float wh1 = sWhh[1][kk][tj];
            const float wh2 = sWhh[2][kk][tj];
            #pragma unroll
            for (int i = 0; i < 4; i++) {
                const float xv = sX[tb * 4 + i][kk];
                const float hv = sH[tb * 4 + i][kk];
                acc[i][0] += xv * wi0;
                acc[i][1] += xv * wi1;
                acc[i][2] += xv * wi2;
                acc[i][3] += hv * wh0;
                acc[i][4] += hv * wh1;
                acc[i][5] += hv * wh2;
            }
        }
        __syncthreads();
    }

    const int j = j0 + tj;
    const float bir  = b_ih[j],          bhr = b_hh[j];
    const float biz  = b_ih[HH + j],     bhz = b_hh[HH + j];
    const float bin_ = b_ih[2 * HH + j], bhn = b_hh[2 * HH + j];
    #pragma unroll
    for (int i = 0; i < 4; i++) {
        const int b = b0 + tb * 4 + i;
        const float r = sigmoidf_(acc[i][0] + bir + acc[i][3] + bhr);
        const float z = sigmoidf_(acc[i][1] + biz + acc[i][4] + bhz);
        const float n = tanhf(acc[i][2] + bin_ + r * (acc[i][5] + bhn));
        const float hp = h[(size_t)b * HH + j];
        h_out[(size_t)b * HH + j] = (1.0f - z) * n + z * hp;
    }
}

// ---------------------------------------------------------------------------
// Projection: out[b][v][t] = hist[t][b][:] . proj_w[v][:] + proj_b[v]
// ---------------------------------------------------------------------------
__global__ __launch_bounds__(512) void proj_kernel(
    const float* __restrict__ proj_w,
    const float* __restrict__ proj_b,
    float* __restrict__ out)
{
    __shared__ float sH[TT][33];
    __shared__ float sW[VV][33];

    const int b   = blockIdx.x;
    const int tid = threadIdx.x;
    const int tg  = tid % 25;
    const int vg  = tid / 25;
    const bool active = (tid < 500);

    float acc[8][5];
    #pragma unroll
    for (int i = 0; i < 8; i++)
        #pragma unroll
        for (int jv = 0; jv < 5; jv++) acc[i][jv] = 0.0f;

    for (int k0 = 0; k0 < HH; k0 += 32) {
        for (int idx = tid; idx < TT * 32; idx += 512) {
            const int t = idx >> 5, k = idx & 31;
            sH[t][k] = g_hist[((size_t)t * BB + b) * HH + k0 + k];
        }
        for (int idx = tid; idx < VV * 32; idx += 512) {
            const int v = idx >> 5, k = idx & 31;
            sW[v][k] = proj_w[(size_t)v * HH + k0 + k];
        }
        __syncthreads();

        if (active) {
            #pragma unroll
            for (int kk = 0; kk < 32; kk++) {
                float wv[5];
                #pragma unroll
                for (int jv = 0; jv < 5; jv++) wv[jv] = sW[vg * 5 + jv][kk];
                #pragma unroll
                for (int i = 0; i < 8; i++) {
                    const float hv = sH[tg + 25 * i][kk];
                    #pragma unroll
                    for (int jv = 0; jv < 5; jv++) acc[i][jv] += hv * wv[jv];
                }
            }
        }
        __syncthreads();
    }

    if (active) {
        float pb[5];
        #pragma unroll
        for (int jv = 0; jv < 5; jv++) pb[jv] = proj_b[vg * 5 + jv];
        #pragma unroll
        for (int i = 0; i < 8; i++) {
            const int t = tg + 25 * i;
            #pragma unroll
            for (int jv = 0; jv < 5; jv++) {
                const int v = vg * 5 + jv;
                out[((size_t)b * VV + v) * TT + t] = acc[i][jv] + pb[jv];
            }
        }
    }
}

// ---------------------------------------------------------------------------
extern "C" void kernel_launch(void* const* d_in, const int* in_sizes, int n_in,
                              void* d_out, int out_size)
{
    (void)in_sizes; (void)n_in; (void)out_size;
    const float* feat   = (const float*)d_in[0];
    const float* embed  = (const float*)d_in[1];
    const float* w_ih   = (const float*)d_in[2];
    const float* w_hh   = (const float*)d_in[3];
    const float* b_ih   = (const float*)d_in[4];
    const float* b_hh   = (const float*)d_in[5];
    const float* proj_w = (const float*)d_in[6];
    const float* proj_b = (const float*)d_in[7];
    float* out = (float*)d_out;

    float* hist = nullptr;
    cudaGetSymbolAddress((void**)&hist, g_hist);
    __nv_bfloat16* hhp = nullptr;
    cudaGetSymbolAddress((void**)&hhp, g_hh);
    __nv_bfloat16* hlp = nullptr;
    cudaGetSymbolAddress((void**)&hlp, g_hl);

    cudaFuncSetAttribute(gru_persistent,
                         cudaFuncAttributeMaxDynamicSharedMemorySize, SMEM_P);

    prep_weights<<<(6 * HH * HH + 255) / 256, 256>>>(w_ih, w_hh);
    reset_ctr_kernel<<<1, 32>>>();

    // step 0: x = embed[SOS=0] broadcast, h = feat  -> hist[0]
    gru_step_kernel<<<dim3(HH / 32, BB / 32), 256>>>(embed, 0, feat,
                                                     w_ih, w_hh, b_ih, b_hh, hist);
    convert_h<<<(BB * HH + 255) / 256, 256>>>(hist, hhp, hlp);   // -> pp slot 0

    // steps 1..199: persistent tensor-core kernel (one wave of 128 blocks)
    gru_persistent<<<dim3(32, 4), THR, SMEM_P>>>(b_ih, b_hh, hist, hhp, hlp);

    proj_kernel<<<BB, 512>>>(proj_w, proj_b, out);
}